// round 12
// baseline (speedup 1.0000x reference)
#include <cuda_runtime.h>

// Problem constants (fixed by the reference)
#define N_GOAL  16384
#define N_OBS   65536
#define N_TASK  8192
#define NE1     1048576
#define NE2     1048576
#define B_GRAPH 256
#define F_DIM   128
#define S_DIM   64

#define CAP1 64     // max degree obs-node  (binomial mean 16;  P(>64)  ~ 1e-20)
#define CAP2 256    // max degree task-node (binomial mean 128; P(>256) ~ 1e-24)

typedef unsigned long long u64;

// ---------------- scratch (static device globals; no allocation) -------------
__device__ float g_ygoal[(size_t)N_GOAL * S_DIM];   // x_goal @ W1           (4 MB)
__device__ float g_hb   [(size_t)N_OBS  * S_DIM];   // x_obs@W1 + b1         (16 MB)
__device__ float g_x1   [(size_t)N_OBS  * S_DIM];   // layer-1 output        (16 MB)
__device__ int   g_pos1 [N_OBS];
__device__ int   g_pos2 [N_TASK];
__device__ int   g_list1[(size_t)N_OBS  * CAP1];    // per-dst src lists (16 MB)
__device__ int   g_list2[(size_t)N_TASK * CAP2];    //                   (8 MB)

// Dynamic smem sizes
#define SMEM_K128 ((128 * 132 + 128 * 72) * 4)   // 104448 B (gmem-A GEMMs)
#define SMEM_K64  ((128 * 68  + 64  * 72) * 4)   // 53248 B  (fused GEMMs)

// ---------------- f32x2 packed FMA helpers (Blackwell FFMA2) -----------------
__device__ __forceinline__ void ffma2(u64& d, u64 a, u64 b) {
    asm("fma.rn.f32x2 %0, %1, %2, %0;" : "+l"(d) : "l"(a), "l"(b));
}
__device__ __forceinline__ u64 bcast2(float a) {
    u64 r;
    asm("mov.b64 %0, {%1, %1};" : "=l"(r) : "r"(__float_as_uint(a)));
    return r;
}
__device__ __forceinline__ float2 unpack2(u64 v) {
    float lo, hi;
    asm("mov.b64 {%0, %1}, %2;" : "=f"(lo), "=f"(hi) : "l"(v));
    return make_float2(lo, hi);
}

// ---------------- bucket build -----------------------------------------------
__global__ void zero_pos_k() {
    int i = blockIdx.x * blockDim.x + threadIdx.x;
    if (i < N_OBS)  g_pos1[i] = 0;
    if (i < N_TASK) g_pos2[i] = 0;
}

__global__ void fill1_k(const int* __restrict__ s1, const int* __restrict__ d1) {
    int t = blockIdx.x * blockDim.x + threadIdx.x;
    if (t >= NE1 / 4) return;
    int4 d = __ldg((const int4*)d1 + t);
    int4 s = __ldg((const int4*)s1 + t);
    int p;
    p = atomicAdd(g_pos1 + d.x, 1); if (p < CAP1) g_list1[(size_t)d.x * CAP1 + p] = s.x;
    p = atomicAdd(g_pos1 + d.y, 1); if (p < CAP1) g_list1[(size_t)d.y * CAP1 + p] = s.y;
    p = atomicAdd(g_pos1 + d.z, 1); if (p < CAP1) g_list1[(size_t)d.z * CAP1 + p] = s.z;
    p = atomicAdd(g_pos1 + d.w, 1); if (p < CAP1) g_list1[(size_t)d.w * CAP1 + p] = s.w;
}

__global__ void fill2_k(const int* __restrict__ s2, const int* __restrict__ d2) {
    int t = blockIdx.x * blockDim.x + threadIdx.x;
    if (t >= NE2 / 4) return;
    int4 d = __ldg((const int4*)d2 + t);
    int4 s = __ldg((const int4*)s2 + t);
    int p;
    p = atomicAdd(g_pos2 + d.x, 1); if (p < CAP2) g_list2[(size_t)d.x * CAP2 + p] = s.x;
    p = atomicAdd(g_pos2 + d.y, 1); if (p < CAP2) g_list2[(size_t)d.y * CAP2 + p] = s.y;
    p = atomicAdd(g_pos2 + d.z, 1); if (p < CAP2) g_list2[(size_t)d.z * CAP2 + p] = s.z;
    p = atomicAdd(g_pos2 + d.w, 1); if (p < CAP2) g_list2[(size_t)d.w * CAP2 + p] = s.w;
}

// ---------------- gather core: warp per row, float2 lanes --------------------
template <int UNROLL>
__device__ __forceinline__ float2 gather_row_f2(
    const float2* __restrict__ feat, const int* __restrict__ lst,
    int deg, int lane)
{
    float2 a[UNROLL];
#pragma unroll
    for (int u = 0; u < UNROLL; u++) a[u] = make_float2(0.f, 0.f);
    int j = 0;
    for (; j + UNROLL <= deg; j += UNROLL) {
        int e[UNROLL];
#pragma unroll
        for (int u = 0; u < UNROLL; u++) e[u] = __ldg(lst + j + u);
#pragma unroll
        for (int u = 0; u < UNROLL; u++) {
            float2 v = __ldg(feat + (size_t)e[u] * 32 + lane);
            a[u].x += v.x; a[u].y += v.y;
        }
    }
    for (; j < deg; j++) {
        int e = __ldg(lst + j);
        float2 v = __ldg(feat + (size_t)e * 32 + lane);
        a[0].x += v.x; a[0].y += v.y;
    }
#pragma unroll
    for (int u = 1; u < UNROLL; u++) { a[0].x += a[u].x; a[0].y += a[u].y; }
    return a[0];
}

// ---------------- GEMM building blocks ---------------------------------------
// W load into split lo/hi smem ([K][36] each) for conflict-free LDS.128.
template <int K>
__device__ __forceinline__ void load_W(const float* __restrict__ W,
                                       float* Wlo, float* Whi, int t)
{
#pragma unroll
    for (int i = 0; i < K / 16; i++) {
        int idx = t + i * 256;
        int r = idx >> 4, c4 = idx & 15;
        float4 v = *(const float4*)(W + (size_t)r * 64 + c4 * 4);
        float* dst = (c4 & 1) ? &Whi[r * 36 + (c4 >> 1) * 4]
                              : &Wlo[r * 36 + (c4 >> 1) * 4];
        *(float4*)dst = v;
    }
}

// Barrier-free inner K loop (As pitch = APITCH), 4x8 per-thread tile, FFMA2.
template <int K, int APITCH>
__device__ __forceinline__ void gemm_inner(
    const float* As, const float* Wlo, const float* Whi,
    int tx, int ty, float acc[4][8])
{
    u64 acc2[4][4];
#pragma unroll
    for (int i = 0; i < 4; i++)
#pragma unroll
        for (int j = 0; j < 4; j++) acc2[i][j] = 0ULL;

#pragma unroll 4
    for (int kb = 0; kb < K / 4; kb++) {
        float a4[4][4];
#pragma unroll
        for (int i = 0; i < 4; i++)
            *(float4*)&a4[i][0] =
                *(const float4*)&As[(ty * 4 + i) * APITCH + kb * 4];
#pragma unroll
        for (int kk = 0; kk < 4; kk++) {
            float4 wl = *(const float4*)&Wlo[(kb * 4 + kk) * 36 + tx * 4];
            float4 wh = *(const float4*)&Whi[(kb * 4 + kk) * 36 + tx * 4];
            u64 w0 = ((const u64*)&wl)[0], w1 = ((const u64*)&wl)[1];
            u64 w2 = ((const u64*)&wh)[0], w3 = ((const u64*)&wh)[1];
#pragma unroll
            for (int i = 0; i < 4; i++) {
                u64 av = bcast2(a4[i][kk]);
                ffma2(acc2[i][0], av, w0);
                ffma2(acc2[i][1], av, w1);
                ffma2(acc2[i][2], av, w2);
                ffma2(acc2[i][3], av, w3);
            }
        }
    }
#pragma unroll
    for (int i = 0; i < 4; i++)
#pragma unroll
        for (int j = 0; j < 4; j++) {
            float2 p = unpack2(acc2[i][j]);
            acc[i][2 * j]     = p.x;
            acc[i][2 * j + 1] = p.y;
        }
}

template <bool OUT_RELU>
__device__ __forceinline__ void gemm_store(
    float* __restrict__ C, const float* __restrict__ bias,
    int row0, int tx, int ty, float acc[4][8])
{
    float bv[8];
#pragma unroll
    for (int j = 0; j < 8; j++) bv[j] = bias ? bias[tx * 8 + j] : 0.f;
#pragma unroll
    for (int i = 0; i < 4; i++) {
        float4 o0, o1;
        o0.x = acc[i][0] + bv[0]; o0.y = acc[i][1] + bv[1];
        o0.z = acc[i][2] + bv[2]; o0.w = acc[i][3] + bv[3];
        o1.x = acc[i][4] + bv[4]; o1.y = acc[i][5] + bv[5];
        o1.z = acc[i][6] + bv[6]; o1.w = acc[i][7] + bv[7];
        if (OUT_RELU) {
            o0.x = fmaxf(o0.x, 0.f); o0.y = fmaxf(o0.y, 0.f);
            o0.z = fmaxf(o0.z, 0.f); o0.w = fmaxf(o0.w, 0.f);
            o1.x = fmaxf(o1.x, 0.f); o1.y = fmaxf(o1.y, 0.f);
            o1.z = fmaxf(o1.z, 0.f); o1.w = fmaxf(o1.w, 0.f);
        }
        float* cp = C + (size_t)(row0 + ty * 4 + i) * 64 + tx * 8;
        *(float4*)cp = o0;
        *(float4*)(cp + 4) = o1;
    }
}

// ---- K=128 GEMMs (A from gmem): ygoal and hb --------------------------------
template <bool HAS_BIAS>
__device__ __forceinline__ void gemm128_body(
    const float* __restrict__ A, const float* __restrict__ W,
    const float* __restrict__ bias, float* __restrict__ C)
{
    extern __shared__ float smem[];
    float* As  = smem;                 // [128][132]
    float* Wlo = As + 128 * 132;       // [128][36]
    float* Whi = Wlo + 128 * 36;
    const int t  = threadIdx.x;
    const int tx = t & 7;
    const int ty = t >> 3;
    int row0 = blockIdx.x * 128;

    load_W<128>(W, Wlo, Whi, t);
#pragma unroll
    for (int i = 0; i < 16; i++) {
        int idx = t + i * 256;
        int r = idx >> 5, c4 = idx & 31;
        float4 v = *(const float4*)(A + (size_t)(row0 + r) * 128 + c4 * 4);
        *(float4*)&As[r * 132 + c4 * 4] = v;
    }
    __syncthreads();

    float acc[4][8];
    gemm_inner<128, 132>(As, Wlo, Whi, tx, ty, acc);
    gemm_store<false>(C, HAS_BIAS ? bias : nullptr, row0, tx, ty, acc);
}

__global__ void __launch_bounds__(256) gemm_ygoal_k(
    const float* __restrict__ xg, const float* __restrict__ W1)
{
    gemm128_body<false>(xg, W1, nullptr, g_ygoal);
}

__global__ void __launch_bounds__(256) gemm_hb_k(
    const float* __restrict__ xo, const float* __restrict__ W1,
    const float* __restrict__ b1)
{
    gemm128_body<true>(xo, W1, b1, g_hb);
}

// ---- FUSED mid: per-block gather1 into smem, then x1 = relu(As@W2+b2) -------
// As row r = relu(hb[row] + sum ygoal[list1[row]]).
__global__ void __launch_bounds__(256) gemm_mid_fused_k(
    const float* __restrict__ W2, const float* __restrict__ b2)
{
    extern __shared__ float smem[];
    float* As  = smem;                 // [128][68]
    float* Wlo = As + 128 * 68;        // [64][36]
    float* Whi = Wlo + 64 * 36;
    const int t  = threadIdx.x;
    const int tx = t & 7;
    const int ty = t >> 3;
    const int wid = t >> 5, lane = t & 31;
    int row0 = blockIdx.x * 128;

    load_W<64>(W2, Wlo, Whi, t);

    // aggregate 16 rows per warp
    for (int rr = 0; rr < 16; rr++) {
        int r = wid * 16 + rr;
        int row = row0 + r;
        int deg = g_pos1[row]; if (deg > CAP1) deg = CAP1;
        float2 s = gather_row_f2<4>((const float2*)g_ygoal,
                                    g_list1 + (size_t)row * CAP1, deg, lane);
        float2 h = __ldg((const float2*)g_hb + (size_t)row * 32 + lane);
        float2 v = make_float2(fmaxf(h.x + s.x, 0.f), fmaxf(h.y + s.y, 0.f));
        *(float2*)&As[r * 68 + lane * 2] = v;
    }
    __syncthreads();

    float acc[4][8];
    gemm_inner<64, 68>(As, Wlo, Whi, tx, ty, acc);
    gemm_store<true>(g_x1, b2, row0, tx, ty, acc);
}

// ---- FUSED tail: per-block gather2 into smem, GEMM3, x2, pool, critic -------
__global__ void __launch_bounds__(256) gemm_tail_fused_k(
    const float* __restrict__ x_task,
    const float* __restrict__ W3, const float* __restrict__ b3,
    const float* __restrict__ W4, const float* __restrict__ b4,
    const float* __restrict__ Wc1, const float* __restrict__ bc1,
    const float* __restrict__ Wc2, const float* __restrict__ bc2,
    float* __restrict__ out)
{
    extern __shared__ float smem[];
    float* As  = smem;                 // [128][68]
    float* Wlo = As + 128 * 68;        // [64][36]
    float* Whi = Wlo + 64 * 36;
    __shared__ float sx2[128];
    const int t  = threadIdx.x;
    const int tx = t & 7;
    const int ty = t >> 3;
    const int wid = t >> 5, lane = t & 31;
    int row0 = blockIdx.x * 128;

    load_W<64>(W3, Wlo, Whi, t);

    // aggregate 16 rows per warp: buf2[row] = x_task[row] + sum x1[list2[row]]
    for (int rr = 0; rr < 16; rr++) {
        int r = wid * 16 + rr;
        int row = row0 + r;
        int deg = g_pos2[row]; if (deg > CAP2) deg = CAP2;
        float2 s = gather_row_f2<8>((const float2*)g_x1,
                                    g_list2 + (size_t)row * CAP2, deg, lane);
        float2 xt = __ldg((const float2*)x_task + (size_t)row * 32 + lane);
        *(float2*)&As[r * 68 + lane * 2] =
            make_float2(xt.x + s.x, xt.y + s.y);
    }
    __syncthreads();

    float acc[4][8];
    gemm_inner<64, 68>(As, Wlo, Whi, tx, ty, acc);

    // x2 = relu(acc + b3) @ W4 + b4, per row; then pool 4 graphs + critic
    float b3v[8], w4v[8];
#pragma unroll
    for (int j = 0; j < 8; j++) {
        b3v[j] = __ldg(b3 + tx * 8 + j);
        w4v[j] = __ldg(W4 + tx * 8 + j);
    }
    float b4s = __ldg(b4);

#pragma unroll
    for (int i = 0; i < 4; i++) {
        float p = 0.f;
#pragma unroll
        for (int j = 0; j < 8; j++)
            p += fmaxf(acc[i][j] + b3v[j], 0.f) * w4v[j];
#pragma unroll
        for (int o = 4; o; o >>= 1) p += __shfl_xor_sync(0xffffffffu, p, o);
        if (tx == 0) sx2[ty * 4 + i] = p + b4s;
    }
    __syncthreads();

    if (wid < 4) {
        float v = sx2[wid * 32 + lane];
        float mx = v, sm = v;
#pragma unroll
        for (int o = 16; o; o >>= 1) {
            mx = fmaxf(mx, __shfl_xor_sync(0xffffffffu, mx, o));
            sm += __shfl_xor_sync(0xffffffffu, sm, o);
        }
        if (lane == 0) {
            float mean = sm * (1.0f / 32.0f);
            float a = __ldg(bc2);
#pragma unroll
            for (int j = 0; j < 8; j++) {
                float hj = fmaxf(mx * __ldg(Wc1 + j) + mean * __ldg(Wc1 + 8 + j)
                                 + __ldg(bc1 + j), 0.f);
                a += hj * __ldg(Wc2 + j);
            }
            out[blockIdx.x * 4 + wid] = a;
        }
    }
}

// ---------------- launch (multi-stream fork/join inside graph capture) -------
extern "C" void kernel_launch(void* const* d_in, const int* in_sizes, int n_in,
                              void* d_out, int out_size) {
    const float* x_goal = (const float*)d_in[0];
    const float* x_obs  = (const float*)d_in[1];
    const float* x_task = (const float*)d_in[2];
    const int* ei_go_src = (const int*)d_in[3];
    const int* ei_go_dst = (const int*)d_in[4];
    const int* ei_ot_src = (const int*)d_in[5];
    const int* ei_ot_dst = (const int*)d_in[6];
    // d_in[7] = task_batch (contiguous arange/32, implicit)
    const float* W1  = (const float*)d_in[8];
    const float* b1  = (const float*)d_in[9];
    const float* W2  = (const float*)d_in[10];
    const float* b2  = (const float*)d_in[11];
    const float* W3  = (const float*)d_in[12];
    const float* b3  = (const float*)d_in[13];
    const float* W4  = (const float*)d_in[14];
    const float* b4  = (const float*)d_in[15];
    const float* Wc1 = (const float*)d_in[16];
    const float* bc1 = (const float*)d_in[17];
    const float* Wc2 = (const float*)d_in[18];
    const float* bc2 = (const float*)d_in[19];
    float* out = (float*)d_out;

    // Lazily created once (first call happens outside graph capture).
    static cudaStream_t s1 = nullptr, s2 = nullptr;
    static cudaEvent_t eRoot = nullptr, eZ = nullptr, eY = nullptr,
                       eHb = nullptr, eF2 = nullptr;
    if (!s1) {
        cudaStreamCreateWithFlags(&s1, cudaStreamNonBlocking);
        cudaStreamCreateWithFlags(&s2, cudaStreamNonBlocking);
        cudaEventCreateWithFlags(&eRoot, cudaEventDisableTiming);
        cudaEventCreateWithFlags(&eZ,    cudaEventDisableTiming);
        cudaEventCreateWithFlags(&eY,    cudaEventDisableTiming);
        cudaEventCreateWithFlags(&eHb,   cudaEventDisableTiming);
        cudaEventCreateWithFlags(&eF2,   cudaEventDisableTiming);
        cudaFuncSetAttribute(gemm_ygoal_k,
            cudaFuncAttributeMaxDynamicSharedMemorySize, SMEM_K128);
        cudaFuncSetAttribute(gemm_hb_k,
            cudaFuncAttributeMaxDynamicSharedMemorySize, SMEM_K128);
        cudaFuncSetAttribute(gemm_mid_fused_k,
            cudaFuncAttributeMaxDynamicSharedMemorySize, SMEM_K64);
        cudaFuncSetAttribute(gemm_tail_fused_k,
            cudaFuncAttributeMaxDynamicSharedMemorySize, SMEM_K64);
    }

    // Fork
    cudaEventRecord(eRoot, 0);
    cudaStreamWaitEvent(s1, eRoot, 0);
    cudaStreamWaitEvent(s2, eRoot, 0);

    // s0: zero counters, then fill1 (critical for mid_fused)
    zero_pos_k<<<(N_OBS + 255) / 256, 256>>>();
    cudaEventRecord(eZ, 0);
    fill1_k<<<(NE1 / 4 + 255) / 256, 256>>>(ei_go_src, ei_go_dst);

    // s1: small ygoal GEMM
    gemm_ygoal_k<<<N_GOAL / 128, 256, SMEM_K128, s1>>>(x_goal, W1);
    cudaEventRecord(eY, s1);

    // s2: big hb GEMM, then fill2 (needs zeroed pos2)
    gemm_hb_k<<<N_OBS / 128, 256, SMEM_K128, s2>>>(x_obs, W1, b1);
    cudaEventRecord(eHb, s2);
    cudaStreamWaitEvent(s2, eZ, 0);
    fill2_k<<<(NE2 / 4 + 255) / 256, 256, 0, s2>>>(ei_ot_src, ei_ot_dst);
    cudaEventRecord(eF2, s2);

    // s0: fused mid (needs fill1 [program order] + ygoal + hb)
    cudaStreamWaitEvent(0, eY, 0);
    cudaStreamWaitEvent(0, eHb, 0);
    gemm_mid_fused_k<<<N_OBS / 128, 256, SMEM_K64>>>(W2, b2);

    // s0: fused tail (needs x1 [program order] + fill2)
    cudaStreamWaitEvent(0, eF2, 0);
    gemm_tail_fused_k<<<N_TASK / 128, 256, SMEM_K64>>>(
        x_task, W3, b3, W4, b4, Wc1, bc1, Wc2, bc2, out);
}

// round 14
// speedup vs baseline: 2.8819x; 2.8819x over previous
#include <cuda_runtime.h>

// Problem constants (fixed by the reference)
#define N_GOAL  16384
#define N_OBS   65536
#define N_TASK  8192
#define NE1     1048576
#define NE2     1048576
#define B_GRAPH 256
#define F_DIM   128
#define S_DIM   64

#define CAP1 64     // max degree obs-node  (binomial mean 16;  P(>64)  ~ 1e-20)
#define CAP2 256    // max degree task-node (binomial mean 128; P(>256) ~ 1e-24)

typedef unsigned long long u64;

// ---------------- scratch (static device globals; no allocation) -------------
__device__ float g_ygoal[(size_t)N_GOAL * S_DIM];   // x_goal @ W1           (4 MB)
__device__ float g_hb   [(size_t)N_OBS  * S_DIM];   // x_obs@W1 + b1         (16 MB)
__device__ float g_agg1 [(size_t)N_OBS  * S_DIM];   // sum ygoal[neigh]      (16 MB)
__device__ float g_x1   [(size_t)N_OBS  * S_DIM];   // relu(relu(hb+agg)@W2+b2)
__device__ float g_buf2 [(size_t)N_TASK * S_DIM];   // x_task + agg2         (2 MB)
__device__ int   g_pos1 [N_OBS];
__device__ int   g_pos2 [N_TASK];
__device__ int   g_list1[(size_t)N_OBS  * CAP1];    // per-dst src lists (16 MB)
__device__ int   g_list2[(size_t)N_TASK * CAP2];    //                   (8 MB)

// ---------------- f32x2 packed FMA helpers (Blackwell FFMA2) -----------------
__device__ __forceinline__ void ffma2(u64& d, u64 a, u64 b) {
    asm("fma.rn.f32x2 %0, %1, %2, %0;" : "+l"(d) : "l"(a), "l"(b));
}
__device__ __forceinline__ u64 bcast2(float a) {
    u64 r;
    asm("mov.b64 %0, {%1, %1};" : "=l"(r) : "r"(__float_as_uint(a)));
    return r;
}
__device__ __forceinline__ float2 unpack2(u64 v) {
    float lo, hi;
    asm("mov.b64 {%0, %1}, %2;" : "=f"(lo), "=f"(hi) : "l"(v));
    return make_float2(lo, hi);
}

// ---------------- bucket build -----------------------------------------------
__global__ void zero_pos_k() {
    int i = blockIdx.x * blockDim.x + threadIdx.x;
    if (i < N_OBS)  g_pos1[i] = 0;
    if (i < N_TASK) g_pos2[i] = 0;
}

// 4 edges per thread, int4 index loads (halves LSU instruction count).
__global__ void fill1_k(const int* __restrict__ s1, const int* __restrict__ d1) {
    int t = blockIdx.x * blockDim.x + threadIdx.x;
    if (t >= NE1 / 4) return;
    int4 d = __ldg((const int4*)d1 + t);
    int4 s = __ldg((const int4*)s1 + t);
    int p;
    p = atomicAdd(g_pos1 + d.x, 1); if (p < CAP1) g_list1[(size_t)d.x * CAP1 + p] = s.x;
    p = atomicAdd(g_pos1 + d.y, 1); if (p < CAP1) g_list1[(size_t)d.y * CAP1 + p] = s.y;
    p = atomicAdd(g_pos1 + d.z, 1); if (p < CAP1) g_list1[(size_t)d.z * CAP1 + p] = s.z;
    p = atomicAdd(g_pos1 + d.w, 1); if (p < CAP1) g_list1[(size_t)d.w * CAP1 + p] = s.w;
}

__global__ void fill2_k(const int* __restrict__ s2, const int* __restrict__ d2) {
    int t = blockIdx.x * blockDim.x + threadIdx.x;
    if (t >= NE2 / 4) return;
    int4 d = __ldg((const int4*)d2 + t);
    int4 s = __ldg((const int4*)s2 + t);
    int p;
    p = atomicAdd(g_pos2 + d.x, 1); if (p < CAP2) g_list2[(size_t)d.x * CAP2 + p] = s.x;
    p = atomicAdd(g_pos2 + d.y, 1); if (p < CAP2) g_list2[(size_t)d.y * CAP2 + p] = s.y;
    p = atomicAdd(g_pos2 + d.z, 1); if (p < CAP2) g_list2[(size_t)d.z * CAP2 + p] = s.z;
    p = atomicAdd(g_pos2 + d.w, 1); if (p < CAP2) g_list2[(size_t)d.w * CAP2 + p] = s.w;
}

// =============================================================================
// Tiled GEMM core: 128x64 tile, 256 threads, 4-row x 8-col thread tile,
// BK=32 chunks, packed fma.rn.f32x2. W tile split lo/hi for conflict-free
// LDS.128 reads. (Exact R8 structure — the 161.9us champion.)
// =============================================================================
template <int K, bool IN_RELU, bool HAS_A2>
__device__ __forceinline__ void gemm_compute(
    const float* __restrict__ A, const float* __restrict__ A2,
    const float* __restrict__ W, int row0, float acc[4][8])
{
    __shared__ float As[128][36];
    __shared__ float Wlo[32][36];   // cols tx*8+0..3 at [k][tx*4..+4]
    __shared__ float Whi[32][36];   // cols tx*8+4..7

    const int t  = threadIdx.x;
    const int tx = t & 7;
    const int ty = t >> 3;

    u64 acc2[4][4];
#pragma unroll
    for (int i = 0; i < 4; i++)
#pragma unroll
        for (int j = 0; j < 4; j++) acc2[i][j] = 0ULL;

#pragma unroll
    for (int k0 = 0; k0 < K; k0 += 32) {
#pragma unroll
        for (int i = 0; i < 4; i++) {
            int idx = t + i * 256;
            int r = idx >> 3, c4 = idx & 7;
            size_t off = (size_t)(row0 + r) * K + k0 + c4 * 4;
            float4 v = *(const float4*)(A + off);
            if (HAS_A2) {
                float4 v2 = *(const float4*)(A2 + off);
                v.x += v2.x; v.y += v2.y; v.z += v2.z; v.w += v2.w;
            }
            if (IN_RELU) {
                v.x = fmaxf(v.x, 0.f); v.y = fmaxf(v.y, 0.f);
                v.z = fmaxf(v.z, 0.f); v.w = fmaxf(v.w, 0.f);
            }
            *(float4*)&As[r][c4 * 4] = v;
        }
#pragma unroll
        for (int i = 0; i < 2; i++) {
            int idx = t + i * 256;
            int r = idx >> 4, c4 = idx & 15;
            float4 v = *(const float4*)(W + (size_t)(k0 + r) * 64 + c4 * 4);
            float* dst = (c4 & 1) ? &Whi[r][(c4 >> 1) * 4]
                                  : &Wlo[r][(c4 >> 1) * 4];
            *(float4*)dst = v;
        }
        __syncthreads();
#pragma unroll
        for (int kb = 0; kb < 8; kb++) {
            float a4[4][4];
#pragma unroll
            for (int i = 0; i < 4; i++)
                *(float4*)&a4[i][0] = *(const float4*)&As[ty * 4 + i][kb * 4];
#pragma unroll
            for (int kk = 0; kk < 4; kk++) {
                float4 wl = *(const float4*)&Wlo[kb * 4 + kk][tx * 4];
                float4 wh = *(const float4*)&Whi[kb * 4 + kk][tx * 4];
                u64 w0 = ((const u64*)&wl)[0], w1 = ((const u64*)&wl)[1];
                u64 w2 = ((const u64*)&wh)[0], w3 = ((const u64*)&wh)[1];
#pragma unroll
                for (int i = 0; i < 4; i++) {
                    u64 av = bcast2(a4[i][kk]);
                    ffma2(acc2[i][0], av, w0);
                    ffma2(acc2[i][1], av, w1);
                    ffma2(acc2[i][2], av, w2);
                    ffma2(acc2[i][3], av, w3);
                }
            }
        }
        __syncthreads();
    }
#pragma unroll
    for (int i = 0; i < 4; i++)
#pragma unroll
        for (int j = 0; j < 4; j++) {
            float2 p = unpack2(acc2[i][j]);
            acc[i][2 * j]     = p.x;
            acc[i][2 * j + 1] = p.y;
        }
}

template <bool OUT_RELU>
__device__ __forceinline__ void gemm_store(
    float* __restrict__ C, const float* __restrict__ bias,
    int row0, float acc[4][8])
{
    const int t  = threadIdx.x;
    const int tx = t & 7;
    const int ty = t >> 3;
    float bv[8];
#pragma unroll
    for (int j = 0; j < 8; j++) bv[j] = bias ? bias[tx * 8 + j] : 0.f;
#pragma unroll
    for (int i = 0; i < 4; i++) {
        float4 o0, o1;
        o0.x = acc[i][0] + bv[0]; o0.y = acc[i][1] + bv[1];
        o0.z = acc[i][2] + bv[2]; o0.w = acc[i][3] + bv[3];
        o1.x = acc[i][4] + bv[4]; o1.y = acc[i][5] + bv[5];
        o1.z = acc[i][6] + bv[6]; o1.w = acc[i][7] + bv[7];
        if (OUT_RELU) {
            o0.x = fmaxf(o0.x, 0.f); o0.y = fmaxf(o0.y, 0.f);
            o0.z = fmaxf(o0.z, 0.f); o0.w = fmaxf(o0.w, 0.f);
            o1.x = fmaxf(o1.x, 0.f); o1.y = fmaxf(o1.y, 0.f);
            o1.z = fmaxf(o1.z, 0.f); o1.w = fmaxf(o1.w, 0.f);
        }
        float* cp = C + (size_t)(row0 + ty * 4 + i) * 64 + tx * 8;
        *(float4*)cp = o0;
        *(float4*)(cp + 4) = o1;
    }
}

// ---- ygoal GEMM: y_goal = x_goal @ W1  (K=128) ------------------------------
__global__ void __launch_bounds__(256, 3) gemm_ygoal_k(
    const float* __restrict__ xg, const float* __restrict__ W1)
{
    float acc[4][8];
    int row0 = blockIdx.x * 128;
    gemm_compute<128, false, false>(xg, nullptr, W1, row0, acc);
    gemm_store<false>(g_ygoal, nullptr, row0, acc);
}

// ---- hb GEMM: hb = x_obs @ W1 + b1  (K=128) ---------------------------------
__global__ void __launch_bounds__(256, 3) gemm_hb_k(
    const float* __restrict__ xo, const float* __restrict__ W1,
    const float* __restrict__ b1)
{
    float acc[4][8];
    int row0 = blockIdx.x * 128;
    gemm_compute<128, false, false>(xo, nullptr, W1, row0, acc);
    gemm_store<false>(g_hb, b1, row0, acc);
}

// ---- GEMM 2: x1 = relu(relu(hb + agg1) @ W2 + b2)  (K=64) -------------------
__global__ void __launch_bounds__(256, 3) gemm_mid_k(
    const float* __restrict__ W2, const float* __restrict__ b2)
{
    float acc[4][8];
    int row0 = blockIdx.x * 128;
    gemm_compute<64, true, true>(g_hb, g_agg1, W2, row0, acc);
    gemm_store<true>(g_x1, b2, row0, acc);
}

// ---- GEMM 3 fused: g=relu(buf2@W3+b3); x2=g@W4+b4; pool 4 graphs; critic ----
__global__ void __launch_bounds__(256, 3) gemm_tail_k(
    const float* __restrict__ W3, const float* __restrict__ b3,
    const float* __restrict__ W4, const float* __restrict__ b4,
    const float* __restrict__ Wc1, const float* __restrict__ bc1,
    const float* __restrict__ Wc2, const float* __restrict__ bc2,
    float* __restrict__ out)
{
    float acc[4][8];
    int row0 = blockIdx.x * 128;
    gemm_compute<64, false, false>(g_buf2, nullptr, W3, row0, acc);

    __shared__ float sx2[128];
    const int t  = threadIdx.x;
    const int tx = t & 7;
    const int ty = t >> 3;
    float b3v[8], w4v[8];
#pragma unroll
    for (int j = 0; j < 8; j++) {
        b3v[j] = __ldg(b3 + tx * 8 + j);
        w4v[j] = __ldg(W4 + tx * 8 + j);
    }
    float b4s = __ldg(b4);

#pragma unroll
    for (int i = 0; i < 4; i++) {
        float p = 0.f;
#pragma unroll
        for (int j = 0; j < 8; j++)
            p += fmaxf(acc[i][j] + b3v[j], 0.f) * w4v[j];
#pragma unroll
        for (int o = 4; o; o >>= 1) p += __shfl_xor_sync(0xffffffffu, p, o);
        if (tx == 0) sx2[ty * 4 + i] = p + b4s;
    }
    __syncthreads();

    int wid = t >> 5, lane = t & 31;
    if (wid < 4) {
        float v = sx2[wid * 32 + lane];
        float mx = v, sm = v;
#pragma unroll
        for (int o = 16; o; o >>= 1) {
            mx = fmaxf(mx, __shfl_xor_sync(0xffffffffu, mx, o));
            sm += __shfl_xor_sync(0xffffffffu, sm, o);
        }
        if (lane == 0) {
            float mean = sm * (1.0f / 32.0f);
            float a = __ldg(bc2);
#pragma unroll
            for (int j = 0; j < 8; j++) {
                float hj = fmaxf(mx * __ldg(Wc1 + j) + mean * __ldg(Wc1 + 8 + j)
                                 + __ldg(bc1 + j), 0.f);
                a += hj * __ldg(Wc2 + j);
            }
            out[blockIdx.x * 4 + wid] = a;
        }
    }
}

// ---------------- gather core: warp per row, float2 lanes, uniform idx loads -
template <int UNROLL>
__device__ __forceinline__ float2 gather_row_f2(
    const float2* __restrict__ feat, const int* __restrict__ lst,
    int deg, int lane)
{
    float2 a[UNROLL];
#pragma unroll
    for (int u = 0; u < UNROLL; u++) a[u] = make_float2(0.f, 0.f);
    int j = 0;
    for (; j + UNROLL <= deg; j += UNROLL) {
        int e[UNROLL];
#pragma unroll
        for (int u = 0; u < UNROLL; u++) e[u] = __ldg(lst + j + u);
#pragma unroll
        for (int u = 0; u < UNROLL; u++) {
            float2 v = __ldg(feat + (size_t)e[u] * 32 + lane);
            a[u].x += v.x; a[u].y += v.y;
        }
    }
    for (; j < deg; j++) {
        int e = __ldg(lst + j);
        float2 v = __ldg(feat + (size_t)e * 32 + lane);
        a[0].x += v.x; a[0].y += v.y;
    }
#pragma unroll
    for (int u = 1; u < UNROLL; u++) { a[0].x += a[u].x; a[0].y += a[u].y; }
    return a[0];
}

// gather1: agg1[d] = sum ygoal[list1[d]]
__global__ void gather1_k() {
    int gid = blockIdx.x * blockDim.x + threadIdx.x;
    int row = gid >> 5, lane = gid & 31;
    if (row >= N_OBS) return;
    int deg = g_pos1[row]; if (deg > CAP1) deg = CAP1;
    float2 s = gather_row_f2<4>((const float2*)g_ygoal,
                                g_list1 + (size_t)row * CAP1, deg, lane);
    ((float2*)g_agg1)[(size_t)row * 32 + lane] = s;
}

// gather2: buf2[d] = x_task[d] + sum x1[list2[d]]
__global__ void gather2_k(const float* __restrict__ x_task) {
    int gid = blockIdx.x * blockDim.x + threadIdx.x;
    int row = gid >> 5, lane = gid & 31;
    if (row >= N_TASK) return;
    int deg = g_pos2[row]; if (deg > CAP2) deg = CAP2;
    float2 s = gather_row_f2<8>((const float2*)g_x1,
                                g_list2 + (size_t)row * CAP2, deg, lane);
    float2 xt = __ldg((const float2*)x_task + (size_t)row * 32 + lane);
    ((float2*)g_buf2)[(size_t)row * 32 + lane] =
        make_float2(xt.x + s.x, xt.y + s.y);
}

// ---------------- launch (multi-stream fork/join inside graph capture) -------
extern "C" void kernel_launch(void* const* d_in, const int* in_sizes, int n_in,
                              void* d_out, int out_size) {
    const float* x_goal = (const float*)d_in[0];
    const float* x_obs  = (const float*)d_in[1];
    const float* x_task = (const float*)d_in[2];
    const int* ei_go_src = (const int*)d_in[3];
    const int* ei_go_dst = (const int*)d_in[4];
    const int* ei_ot_src = (const int*)d_in[5];
    const int* ei_ot_dst = (const int*)d_in[6];
    // d_in[7] = task_batch (contiguous arange/32, implicit)
    const float* W1  = (const float*)d_in[8];
    const float* b1  = (const float*)d_in[9];
    const float* W2  = (const float*)d_in[10];
    const float* b2  = (const float*)d_in[11];
    const float* W3  = (const float*)d_in[12];
    const float* b3  = (const float*)d_in[13];
    const float* W4  = (const float*)d_in[14];
    const float* b4  = (const float*)d_in[15];
    const float* Wc1 = (const float*)d_in[16];
    const float* bc1 = (const float*)d_in[17];
    const float* Wc2 = (const float*)d_in[18];
    const float* bc2 = (const float*)d_in[19];
    float* out = (float*)d_out;

    // Lazily created once (first call happens outside graph capture).
    static cudaStream_t s1 = nullptr, s2 = nullptr;
    static cudaEvent_t eRoot = nullptr, eZ = nullptr, eY = nullptr,
                       eHb = nullptr, eF2 = nullptr;
    if (!s1) {
        cudaStreamCreateWithFlags(&s1, cudaStreamNonBlocking);
        cudaStreamCreateWithFlags(&s2, cudaStreamNonBlocking);
        cudaEventCreateWithFlags(&eRoot, cudaEventDisableTiming);
        cudaEventCreateWithFlags(&eZ,    cudaEventDisableTiming);
        cudaEventCreateWithFlags(&eY,    cudaEventDisableTiming);
        cudaEventCreateWithFlags(&eHb,   cudaEventDisableTiming);
        cudaEventCreateWithFlags(&eF2,   cudaEventDisableTiming);
    }

    // Fork
    cudaEventRecord(eRoot, 0);
    cudaStreamWaitEvent(s1, eRoot, 0);
    cudaStreamWaitEvent(s2, eRoot, 0);

    // s0: zero counters, then fill1 (critical for gather1)
    zero_pos_k<<<(N_OBS + 255) / 256, 256>>>();
    cudaEventRecord(eZ, 0);
    fill1_k<<<(NE1 / 4 + 255) / 256, 256>>>(ei_go_src, ei_go_dst);

    // s1: small ygoal GEMM
    gemm_ygoal_k<<<N_GOAL / 128, 256, 0, s1>>>(x_goal, W1);
    cudaEventRecord(eY, s1);

    // s2: big hb GEMM, then fill2 (needs zeroed pos2)
    gemm_hb_k<<<N_OBS / 128, 256, 0, s2>>>(x_obs, W1, b1);
    cudaEventRecord(eHb, s2);
    cudaStreamWaitEvent(s2, eZ, 0);
    fill2_k<<<(NE2 / 4 + 255) / 256, 256, 0, s2>>>(ei_ot_src, ei_ot_dst);
    cudaEventRecord(eF2, s2);

    // s0: gather1 (needs fill1 [program order] + ygoal)
    cudaStreamWaitEvent(0, eY, 0);
    gather1_k<<<N_OBS * 32 / 256, 256>>>();

    // s0: gemm_mid (needs hb + agg1)
    cudaStreamWaitEvent(0, eHb, 0);
    gemm_mid_k<<<N_OBS / 128, 256>>>(W2, b2);

    // s0: gather2 (needs x1 [program order] + fill2)
    cudaStreamWaitEvent(0, eF2, 0);
    gather2_k<<<N_TASK * 32 / 256, 256>>>(x_task);

    // s0: tail
    gemm_tail_k<<<N_TASK / 128, 256>>>(W3, b3, W4, b4, Wc1, bc1, Wc2, bc2, out);
}